// round 11
// baseline (speedup 1.0000x reference)
#include <cuda_runtime.h>

#define NLAYERS 7
#define EPS_F 1e-5f

// Shapes (fixed by setup_inputs): bsz=8, C=8, QL=KL=128, A=8, cross_range=2
// pw / out: [64, 1024, 1024] f32;  conv_w: [7,8,8,1,3]; conv_b: [7,8]; prelu_a: [7]
//
// Heterogeneous grid, 2048 CTAs, region r = blockIdx>>1 = (b, q):
//   even CTAs: pure zero streamers. Write the 248 dead float4-columns of
//     region r (cols k with k-i not in {+-1,+-2}), 64 rows each, coalesced
//     STG.128, no barriers/SMEM/shfl -- memset-shaped.
//   odd CTAs: compute. Register-resident 7-layer residual conv via
//     __shfl_sync, then write ONLY the live band values (2 STG.128/thread).
// Address sets are disjoint -> no cross-CTA ordering needed. Zero background
// is exact: expm1(0)=0, 0/(sum+eps)=0.

__device__ __forceinline__ void stcs4(float* p, float4 v) {
    asm volatile("st.global.cs.v4.f32 [%0], {%1,%2,%3,%4};"
                 :: "l"(p), "f"(v.x), "f"(v.y), "f"(v.z), "f"(v.w) : "memory");
}

__global__ __launch_bounds__(256, 4)
void sag_split(const float* __restrict__ pw,
               const float* __restrict__ conv_w,
               const float* __restrict__ conv_b,
               const float* __restrict__ prelu_a,
               float* __restrict__ out)
{
    const int tid = threadIdx.x;
    const int r = blockIdx.x >> 1;          // region
    const int b = r >> 7;                   // batch
    const int i = r & 127;                  // query index
    const size_t base = ((size_t)(b * 8) * 1024 + (size_t)i * 8) * 1024;

    // ================= ZERO-STREAMER CTA (even blockIdx) =================
    if ((blockIdx.x & 1) == 0) {
        const int d = (tid >> 1) - i;       // block-col offset of this column
        const bool live = (d == 1) || (d == -1) || (d == 2) || (d == -2);
        if (!live) {
            const float4 z = make_float4(0.f, 0.f, 0.f, 0.f);
            float* col = out + base + (size_t)tid * 4;
            #pragma unroll 2
            for (int rc = 0; rc < 8; rc++) {
                float* pr = col + (size_t)rc * (1024 * 1024);
                #pragma unroll
                for (int rh = 0; rh < 8; rh++)
                    stcs4(pr + rh * 1024, z);
            }
        }
        return;
    }

    // ================= COMPUTE CTA (odd blockIdx) =================
    __shared__ float4 sW4[NLAYERS][8][8];   // [l][ci][co] = (k0,k1,k2,_)
    __shared__ float  sB [NLAYERS][8];
    __shared__ float  sA [NLAYERS];
    __shared__ float  sPS[4][8][8];         // partial row sums [pp][hh][co]
    __shared__ float  sInv[8][8];           // 1/(rowsum+eps)   [hh][co]

    // roles: slab = pp*8+hh (8 lanes per slab), co = lane&7
    const int slab = tid >> 3;
    const int co   = tid & 7;
    const int pp   = slab >> 3;
    const int hh   = slab & 7;
    const int doff = (pp < 2) ? (pp - 2) : (pp - 1);  // {-2,-1,1,2}
    const int j    = i + doff;
    const bool pvalid = (j >= 0) && (j < 128);

    // x load first
    float4 v0 = make_float4(0.f,0.f,0.f,0.f), v1 = v0;
    if (pvalid) {
        const float* srcx = pw +
            ((size_t)((b * 8 + co) * 1024 + (i * 8 + hh)) * 1024 + (size_t)j * 8);
        v0 = *(const float4*)srcx;
        v1 = *(const float4*)(srcx + 4);
    }

    // conv params -> SMEM
    for (int t = tid; t < NLAYERS * 64; t += 256) {
        const int l = t >> 6, rem = t & 63, wco = rem >> 3, wci = rem & 7;
        const float* s = conv_w + ((l * 8 + wco) * 8 + wci) * 3;
        sW4[l][wci][wco] = make_float4(s[0], s[1], s[2], 0.f);
    }
    if (tid < NLAYERS * 8) (&sB[0][0])[tid] = conv_b[tid];
    if (tid < NLAYERS)     sA[tid] = prelu_a[tid];
    __syncthreads();

    float x[8] = {v0.x, v0.y, v0.z, v0.w, v1.x, v1.y, v1.z, v1.w};
    float c[8];
    #pragma unroll
    for (int w = 0; w < 8; w++) c[w] = x[w];

    const int gbase = (tid & 31) & 24;      // slab group base lane

    // 7-layer residual conv, register-resident via shuffles
    #pragma unroll 1
    for (int l = 0; l < NLAYERS; l++) {
        const float bias = sB[l][co];
        float acc[8];
        #pragma unroll
        for (int w = 0; w < 8; w++) acc[w] = bias;

        #pragma unroll
        for (int ci = 0; ci < 8; ci++) {
            const float4 wv = sW4[l][ci][co];
            const int src = gbase | ci;
            const float r0 = __shfl_sync(0xffffffffu, c[0], src);
            const float r1 = __shfl_sync(0xffffffffu, c[1], src);
            const float r2 = __shfl_sync(0xffffffffu, c[2], src);
            const float r3 = __shfl_sync(0xffffffffu, c[3], src);
            const float r4 = __shfl_sync(0xffffffffu, c[4], src);
            const float r5 = __shfl_sync(0xffffffffu, c[5], src);
            const float r6 = __shfl_sync(0xffffffffu, c[6], src);
            const float r7 = __shfl_sync(0xffffffffu, c[7], src);
            acc[0] += wv.y * r0 + wv.z * r1;
            acc[1] += wv.x * r0 + wv.y * r1 + wv.z * r2;
            acc[2] += wv.x * r1 + wv.y * r2 + wv.z * r3;
            acc[3] += wv.x * r2 + wv.y * r3 + wv.z * r4;
            acc[4] += wv.x * r3 + wv.y * r4 + wv.z * r5;
            acc[5] += wv.x * r4 + wv.y * r5 + wv.z * r6;
            acc[6] += wv.x * r5 + wv.y * r6 + wv.z * r7;
            acc[7] += wv.x * r6 + wv.y * r7;
        }

        const float pa = sA[l];
        #pragma unroll
        for (int w = 0; w < 8; w++) {
            const float y = (acc[w] >= 0.f) ? acc[w] : pa * acc[w];
            c[w] = y + c[w];                // residual, in place
        }
    }

    // we = expm1(relu(x - sigmoid(conv)) * (1-eye))
    float we[8];
    float partial = 0.f;
    #pragma unroll
    for (int w = 0; w < 8; w++) {
        const float sg = 1.f / (1.f + __expf(-c[w]));
        float sp = fmaxf(x[w] - sg, 0.f);
        if (hh == w) sp = 0.f;              // self mask
        float v = expm1f(sp);
        if (!pvalid) v = 0.f;
        we[w] = v;
        partial += v;
    }
    sPS[pp][hh][co] = partial;
    __syncthreads();

    if (tid < 64) {
        const int th = tid >> 3, tc = tid & 7;
        const float s = sPS[0][th][tc] + sPS[1][th][tc] + sPS[2][th][tc] + sPS[3][th][tc];
        sInv[th][tc] = 1.f / (s + EPS_F);
    }
    __syncthreads();

    // band store straight from registers (disjoint from streamer columns)
    if (pvalid) {
        const float inv = sInv[hh][co];
        float* dst = out +
            ((size_t)((b * 8 + co) * 1024 + (i * 8 + hh)) * 1024 + (size_t)j * 8);
        stcs4(dst,     make_float4(we[0]*inv, we[1]*inv, we[2]*inv, we[3]*inv));
        stcs4(dst + 4, make_float4(we[4]*inv, we[5]*inv, we[6]*inv, we[7]*inv));
    }
}

extern "C" void kernel_launch(void* const* d_in, const int* in_sizes, int n_in,
                              void* d_out, int out_size) {
    const float* pw = (const float*)d_in[0];
    const float* cw = (const float*)d_in[1];
    const float* cb = (const float*)d_in[2];
    const float* pa = (const float*)d_in[3];
    sag_split<<<2048, 256>>>(pw, cw, cb, pa, (float*)d_out);
}

// round 12
// speedup vs baseline: 1.2614x; 1.2614x over previous
#include <cuda_runtime.h>

#define NLAYERS 7
#define EPS_F 1e-5f

// Shapes (fixed by setup_inputs): bsz=8, C=8, QL=KL=128, A=8, cross_range=2
// pw / out: [64, 1024, 1024] f32;  conv_w: [7,8,8,1,3]; conv_b: [7,8]; prelu_a: [7]
//
// One CTA per (b, q). Register-resident 7-layer residual conv via __shfl_sync
// (channels live in 8 consecutive lanes). Zero stores for the 248 dead
// float4-columns interleaved one 8-row slice per conv layer. Band values
// stored straight from registers. Reg-dieted (rolling shuffle window,
// launch_bounds minBlocks=5) to fit 5 CTAs/SM.

__device__ __forceinline__ void stcs4(float* p, float4 v) {
    asm volatile("st.global.cs.v4.f32 [%0], {%1,%2,%3,%4};"
                 :: "l"(p), "f"(v.x), "f"(v.y), "f"(v.z), "f"(v.w) : "memory");
}

__global__ __launch_bounds__(256, 5)
void sag_shfl5(const float* __restrict__ pw,
               const float* __restrict__ conv_w,
               const float* __restrict__ conv_b,
               const float* __restrict__ prelu_a,
               float* __restrict__ out)
{
    __shared__ float4 sW4[NLAYERS][8][8];   // [l][ci][co] = (k0,k1,k2,_)
    __shared__ float  sB [NLAYERS][8];
    __shared__ float  sA [NLAYERS];
    __shared__ float  sPS[4][8][8];         // partial row sums [pp][hh][co]
    __shared__ float  sInv[8][8];           // 1/(rowsum+eps)   [hh][co]

    const int tid = threadIdx.x;
    const int b = blockIdx.x >> 7;          // batch
    const int i = blockIdx.x & 127;         // query index
    const size_t base = ((size_t)(b * 8) * 1024 + (size_t)i * 8) * 1024;

    // compute roles: slab = pp*8+hh (8 lanes per slab), co = lane&7
    const int co   = tid & 7;
    const int pp   = tid >> 6;              // slab>>3 == tid>>6
    const int hh   = (tid >> 3) & 7;
    const int doff = (pp < 2) ? (pp - 2) : (pp - 1);  // {-2,-1,1,2}
    const int j    = i + doff;
    const bool pvalid = (j >= 0) && (j < 128);

    // ---- x load issued first ----
    float4 v0 = make_float4(0.f,0.f,0.f,0.f), v1 = v0;
    if (pvalid) {
        const float* srcx = pw +
            ((size_t)((b * 8 + co) * 1024 + (i * 8 + hh)) * 1024 + (size_t)j * 8);
        v0 = *(const float4*)srcx;
        v1 = *(const float4*)(srcx + 4);
    }

    // store roles: float4-column = tid; zero columns are d==0 or |d|>2
    const int d = (tid >> 1) - i;
    const bool zcol = (d == 0) || (d < -2) || (d > 2);
    float* colbase = out + base + (size_t)tid * 4;
    const float4 z = make_float4(0.f, 0.f, 0.f, 0.f);

    // ---- zero slice 0 (channel row 0) ----
    if (zcol) {
        #pragma unroll
        for (int rh = 0; rh < 8; rh++) stcs4(colbase + rh * 1024, z);
    }

    // ---- conv params -> SMEM ----
    for (int t = tid; t < NLAYERS * 64; t += 256) {
        const int l = t >> 6, rem = t & 63, wco = rem >> 3, wci = rem & 7;
        const float* s = conv_w + ((l * 8 + wco) * 8 + wci) * 3;
        sW4[l][wci][wco] = make_float4(s[0], s[1], s[2], 0.f);
    }
    if (tid < NLAYERS * 8) (&sB[0][0])[tid] = conv_b[tid];
    if (tid < NLAYERS)     sA[tid] = prelu_a[tid];
    __syncthreads();

    float x[8] = {v0.x, v0.y, v0.z, v0.w, v1.x, v1.y, v1.z, v1.w};
    float c[8];
    #pragma unroll
    for (int w = 0; w < 8; w++) c[w] = x[w];

    const int gbase = (tid & 31) & 24;      // slab group base lane

    // ---- 7-layer residual conv, rolling 3-reg shuffle window ----
    #pragma unroll 1
    for (int l = 0; l < NLAYERS; l++) {
        const float bias = sB[l][co];
        float acc[8];
        #pragma unroll
        for (int w = 0; w < 8; w++) acc[w] = bias;

        #pragma unroll
        for (int ci = 0; ci < 8; ci++) {
            const float4 wv = sW4[l][ci][co];
            const int src = gbase | ci;
            float ra = __shfl_sync(0xffffffffu, c[0], src);
            float rb = __shfl_sync(0xffffffffu, c[1], src);
            acc[0] += wv.y * ra + wv.z * rb;
            #pragma unroll
            for (int w = 1; w < 7; w++) {
                const float rc = __shfl_sync(0xffffffffu, c[w + 1], src);
                acc[w] += wv.x * ra + wv.y * rb + wv.z * rc;
                ra = rb; rb = rc;
            }
            acc[7] += wv.x * ra + wv.y * rb;
        }

        // interleaved zero slice (channel row l+1) — independent of conv data
        if (zcol) {
            float* pr = colbase + (size_t)(l + 1) * (1024 * 1024);
            #pragma unroll
            for (int rh = 0; rh < 8; rh++) stcs4(pr + rh * 1024, z);
        }

        const float pa = sA[l];
        #pragma unroll
        for (int w = 0; w < 8; w++) {
            const float y = (acc[w] >= 0.f) ? acc[w] : pa * acc[w];
            c[w] = y + c[w];                // residual, in place
        }
    }

    // ---- we = exp(relu(x - sigmoid(conv)))-1, masked; reuse x[] for we ----
    float partial = 0.f;
    #pragma unroll
    for (int w = 0; w < 8; w++) {
        const float sg = 1.f / (1.f + __expf(-c[w]));
        float sp = fmaxf(x[w] - sg, 0.f);
        if (hh == w) sp = 0.f;              // self mask
        float v = __expf(sp) - 1.f;         // sp >= 0: safe expm1 substitute
        if (!pvalid) v = 0.f;
        x[w] = v;                           // x now holds we
        partial += v;
    }
    sPS[pp][hh][co] = partial;
    __syncthreads();

    if (tid < 64) {
        const int th = tid >> 3, tc = tid & 7;
        const float s = sPS[0][th][tc] + sPS[1][th][tc] + sPS[2][th][tc] + sPS[3][th][tc];
        sInv[th][tc] = 1.f / (s + EPS_F);
    }
    __syncthreads();

    // ---- band store straight from registers ----
    if (pvalid) {
        const float inv = sInv[hh][co];
        float* dst = out +
            ((size_t)((b * 8 + co) * 1024 + (i * 8 + hh)) * 1024 + (size_t)j * 8);
        stcs4(dst,     make_float4(x[0]*inv, x[1]*inv, x[2]*inv, x[3]*inv));
        stcs4(dst + 4, make_float4(x[4]*inv, x[5]*inv, x[6]*inv, x[7]*inv));
    }
}

extern "C" void kernel_launch(void* const* d_in, const int* in_sizes, int n_in,
                              void* d_out, int out_size) {
    const float* pw = (const float*)d_in[0];
    const float* cw = (const float*)d_in[1];
    const float* cb = (const float*)d_in[2];
    const float* pa = (const float*)d_in[3];
    sag_shfl5<<<1024, 256>>>(pw, cw, cb, pa, (float*)d_out);
}

// round 13
// speedup vs baseline: 1.2968x; 1.0281x over previous
#include <cuda_runtime.h>

#define NLAYERS 7
#define EPS_F 1e-5f

// Shapes (fixed by setup_inputs): bsz=8, C=8, QL=KL=128, A=8, cross_range=2
// pw / out: [64, 1024, 1024] f32;  conv_w: [7,8,8,1,3]; conv_b: [7,8]; prelu_a: [7]
//
// One CTA per (b, q). Register-resident 7-layer residual conv via __shfl_sync.
// Zero fill is ROW-SEQUENTIAL (memset-shaped): warp w in slice s streams the
// full 4KB output row (channel s, agent-row w) as 8 contiguous 512B stores --
// no holes, no predication. Slices are interleaved one per conv layer so DRAM
// is fed continuously. Band values overwrite their 8 floats after the
// __syncthreads (same-CTA cross-thread store ordering via barrier).

__device__ __forceinline__ void stcs4(float* p, float4 v) {
    asm volatile("st.global.cs.v4.f32 [%0], {%1,%2,%3,%4};"
                 :: "l"(p), "f"(v.x), "f"(v.y), "f"(v.z), "f"(v.w) : "memory");
}

__global__ __launch_bounds__(256, 5)
void sag_rows(const float* __restrict__ pw,
              const float* __restrict__ conv_w,
              const float* __restrict__ conv_b,
              const float* __restrict__ prelu_a,
              float* __restrict__ out)
{
    __shared__ float4 sW4[NLAYERS][8][8];   // [l][ci][co] = (k0,k1,k2,_)
    __shared__ float  sB [NLAYERS][8];
    __shared__ float  sA [NLAYERS];
    __shared__ float  sPS[4][8][8];         // partial row sums [pp][hh][co]
    __shared__ float  sInv[8][8];           // 1/(rowsum+eps)   [hh][co]

    const int tid  = threadIdx.x;
    const int lane = tid & 31;
    const int wrp  = tid >> 5;              // warp id 0..7
    const int b = blockIdx.x >> 7;          // batch
    const int i = blockIdx.x & 127;         // query index
    const size_t base = ((size_t)(b * 8) * 1024 + (size_t)i * 8) * 1024;

    // zero-stream base for this warp: row (channel s, agent-row wrp)
    // slice s offset = s*1MB + wrp*4KB; within row, lane*4 + g*128 floats
    float* zrow0 = out + base + (size_t)wrp * 1024 + lane * 4;
    const float4 z = make_float4(0.f, 0.f, 0.f, 0.f);

    // compute roles: slab = pp*8+hh (8 lanes per slab), co = lane&7
    const int co   = tid & 7;
    const int pp   = tid >> 6;
    const int hh   = (tid >> 3) & 7;
    const int doff = (pp < 2) ? (pp - 2) : (pp - 1);  // {-2,-1,1,2}
    const int j    = i + doff;
    const bool pvalid = (j >= 0) && (j < 128);

    // ---- x load issued first ----
    float4 v0 = make_float4(0.f,0.f,0.f,0.f), v1 = v0;
    if (pvalid) {
        const float* srcx = pw +
            ((size_t)((b * 8 + co) * 1024 + (i * 8 + hh)) * 1024 + (size_t)j * 8);
        v0 = *(const float4*)srcx;
        v1 = *(const float4*)(srcx + 4);
    }

    // ---- zero slice 0: channel 0, full 4KB row per warp, sequential ----
    {
        float* p = zrow0;
        #pragma unroll
        for (int g = 0; g < 8; g++) stcs4(p + g * 128, z);
    }

    // ---- conv params -> SMEM ----
    for (int t = tid; t < NLAYERS * 64; t += 256) {
        const int l = t >> 6, rem = t & 63, wco = rem >> 3, wci = rem & 7;
        const float* s = conv_w + ((l * 8 + wco) * 8 + wci) * 3;
        sW4[l][wci][wco] = make_float4(s[0], s[1], s[2], 0.f);
    }
    if (tid < NLAYERS * 8) (&sB[0][0])[tid] = conv_b[tid];
    if (tid < NLAYERS)     sA[tid] = prelu_a[tid];
    __syncthreads();

    float x[8] = {v0.x, v0.y, v0.z, v0.w, v1.x, v1.y, v1.z, v1.w};
    float c[8];
    #pragma unroll
    for (int w = 0; w < 8; w++) c[w] = x[w];

    const int gbase = lane & 24;            // slab group base lane

    // ---- 7-layer residual conv, rolling 3-reg shuffle window ----
    #pragma unroll 1
    for (int l = 0; l < NLAYERS; l++) {
        const float bias = sB[l][co];
        float acc[8];
        #pragma unroll
        for (int w = 0; w < 8; w++) acc[w] = bias;

        #pragma unroll
        for (int ci = 0; ci < 8; ci++) {
            const float4 wv = sW4[l][ci][co];
            const int src = gbase | ci;
            float ra = __shfl_sync(0xffffffffu, c[0], src);
            float rb = __shfl_sync(0xffffffffu, c[1], src);
            acc[0] += wv.y * ra + wv.z * rb;
            #pragma unroll
            for (int w = 1; w < 7; w++) {
                const float rc = __shfl_sync(0xffffffffu, c[w + 1], src);
                acc[w] += wv.x * ra + wv.y * rb + wv.z * rc;
                ra = rb; rb = rc;
            }
            acc[7] += wv.x * ra + wv.y * rb;
        }

        // interleaved zero slice: channel l+1, full row, sequential
        {
            float* p = zrow0 + (size_t)(l + 1) * (1024 * 1024);
            #pragma unroll
            for (int g = 0; g < 8; g++) stcs4(p + g * 128, z);
        }

        const float pa = sA[l];
        #pragma unroll
        for (int w = 0; w < 8; w++) {
            const float y = (acc[w] >= 0.f) ? acc[w] : pa * acc[w];
            c[w] = y + c[w];                // residual, in place
        }
    }

    // ---- we = exp(relu(x - sigmoid(conv)))-1, masked; reuse x[] ----
    float partial = 0.f;
    #pragma unroll
    for (int w = 0; w < 8; w++) {
        const float sg = 1.f / (1.f + __expf(-c[w]));
        float sp = fmaxf(x[w] - sg, 0.f);
        if (hh == w) sp = 0.f;              // self mask
        float v = __expf(sp) - 1.f;         // sp >= 0
        if (!pvalid) v = 0.f;
        x[w] = v;
        partial += v;
    }
    sPS[pp][hh][co] = partial;
    __syncthreads();

    if (tid < 64) {
        const int th = tid >> 3, tc = tid & 7;
        const float s = sPS[0][th][tc] + sPS[1][th][tc] + sPS[2][th][tc] + sPS[3][th][tc];
        sInv[th][tc] = 1.f / (s + EPS_F);
    }
    __syncthreads();   // also orders zero stores before band overwrite

    // ---- band store overwrites its 8 floats (ordered by the barrier) ----
    if (pvalid) {
        const float inv = sInv[hh][co];
        float* dst = out +
            ((size_t)((b * 8 + co) * 1024 + (i * 8 + hh)) * 1024 + (size_t)j * 8);
        stcs4(dst,     make_float4(x[0]*inv, x[1]*inv, x[2]*inv, x[3]*inv));
        stcs4(dst + 4, make_float4(x[4]*inv, x[5]*inv, x[6]*inv, x[7]*inv));
    }
}

extern "C" void kernel_launch(void* const* d_in, const int* in_sizes, int n_in,
                              void* d_out, int out_size) {
    const float* pw = (const float*)d_in[0];
    const float* cw = (const float*)d_in[1];
    const float* cb = (const float*)d_in[2];
    const float* pa = (const float*)d_in[3];
    sag_rows<<<1024, 256>>>(pw, cw, cb, pa, (float*)d_out);
}